// round 3
// baseline (speedup 1.0000x reference)
#include <cuda_runtime.h>
#include <cstdint>
#include <math.h>

#define PI_D 3.14159265358979323846

// ---------------- dimensions ----------------
// B=4, C=128, Cg=64, Cl=64, Ci=32, H=W=256
// FU1: N=256, Wf=129, S=33024 ; FU2: N=128, Wf=65, S=8320

// ---------------- scratch (device globals; allocation-free) ----------------
__device__ __align__(16) float  g_yin [4*32*65536];       // y_in (4,32,256,256)
__device__ __align__(16) float  g_ysg [4*32*128*128];     // quadrant-stacked (4,32,128,128)
__device__ __align__(16) float2 g_F1  [4*32*256*129];     // FU1 spectrum / G
__device__ __align__(16) float2 g_F2  [4*32*128*65];      // FU2 spectrum / G
__device__ __align__(16) float  g_YC1 [4*64*256*129];     // FU1 freq conv out
__device__ __align__(16) float  g_YC2 [4*64*128*65];      // FU2 freq conv out
__device__ __align__(16) float  g_yg  [4*32*65536];       // FU1 output (spatial)
__device__ __align__(16) float  g_yfu2[4*32*128*128];     // FU2 output (spatial)
__device__ __align__(16) float  g_Wbig[160*128];
__device__ float  g_bbig[160];
__device__ float2 g_tw256[128];
__device__ float2 g_tw128[64];
__device__ float  g_part1[4*64*2];
__device__ float  g_part2[4*64*2];
__device__ float  g_scale1[64], g_shift1[64];
__device__ float  g_scale2[64], g_shift2[64];

// ---------------- prep: twiddles + fused weight matrix ----------------
__global__ void k_prep(const float* __restrict__ w_local, const float* __restrict__ b_local,
                       const float* __restrict__ w_in,    const float* __restrict__ b_in,
                       const float* __restrict__ w_g2l,   const float* __restrict__ b_g2l,
                       const float* __restrict__ w_l2g,   const float* __restrict__ b_l2g) {
    int t = threadIdx.x;
    for (int i = t; i < 128; i += 256) {
        double a = -2.0 * PI_D * (double)i / 256.0;
        g_tw256[i] = make_float2((float)cos(a), (float)sin(a));
    }
    for (int i = t; i < 64; i += 256) {
        double a = -2.0 * PI_D * (double)i / 128.0;
        g_tw128[i] = make_float2((float)cos(a), (float)sin(a));
    }
    for (int i = t; i < 160*128; i += 256) {
        int row = i >> 7, c = i & 127; float v;
        if (row < 64)        v = (c >= 64) ? w_l2g[row*64 + (c-64)] : 0.f;          // Y_g init = l2g(x_l)
        else if (row < 128) { int o = row-64; v = (c < 64) ? w_g2l[o*64+c] : w_local[o*64 + (c-64)]; } // Y_l
        else               { int o = row-128; v = (c < 64) ? w_in[o*64+c] : 0.f; }  // y_in
        g_Wbig[i] = v;
    }
    for (int i = t; i < 160; i += 256) {
        float v;
        if (i < 64)       v = b_l2g[i];
        else if (i < 128) v = b_g2l[i-64] + b_local[i-64];
        else              v = b_in[i-128];
        g_bbig[i] = v;
    }
}

// ---------------- main fused conv: x -> d_out(128ch init) + y_in(32ch) ----------------
// 160x128 pixel-wise GEMM, 64-pixel tiles, 256 threads, each 10 rows x 4 px
__global__ void k_conv_main(const float* __restrict__ x, float* __restrict__ out) {
    extern __shared__ __align__(16) float sm[];
    float* Ws = sm;              // 160*129
    float* Xs = sm + 160*129;    // 128*64
    int b  = blockIdx.y;
    int p0 = blockIdx.x * 64;
    int t  = threadIdx.x;
    for (int i = t; i < 160*128; i += 256) Ws[(i>>7)*129 + (i&127)] = g_Wbig[i];
    const float* xb = x + (size_t)b*128*65536 + p0;
    for (int i = t; i < 128*64; i += 256) {
        int c = i >> 6, p = i & 63;
        Xs[i] = xb[(size_t)c*65536 + p];
    }
    __syncthreads();
    int rg = t >> 4, pg = t & 15;
    float acc[10][4];
    #pragma unroll
    for (int r = 0; r < 10; r++) { acc[r][0]=acc[r][1]=acc[r][2]=acc[r][3]=0.f; }
    const float* wp = Ws + rg*10*129;
    #pragma unroll 4
    for (int k = 0; k < 128; k++) {
        float4 xf = *(const float4*)&Xs[k*64 + pg*4];
        #pragma unroll
        for (int r = 0; r < 10; r++) {
            float wv = wp[r*129 + k];
            acc[r][0] += wv*xf.x; acc[r][1] += wv*xf.y;
            acc[r][2] += wv*xf.z; acc[r][3] += wv*xf.w;
        }
    }
    #pragma unroll
    for (int r = 0; r < 10; r++) {
        int row = rg*10 + r;
        float bo = g_bbig[row];
        float4 res = make_float4(acc[r][0]+bo, acc[r][1]+bo, acc[r][2]+bo, acc[r][3]+bo);
        if (row < 128) *(float4*)&out  [(size_t)(b*128+row)*65536     + p0 + pg*4] = res;
        else           *(float4*)&g_yin[(size_t)(b*32 +row-128)*65536 + p0 + pg*4] = res;
    }
}

// ---------------- quadrant stack for FU2 ----------------
__global__ void k_quad() {
    int idx = blockIdx.x*256 + threadIdx.x;           // total 4*32*128*128 = 2^21
    int w  = idx & 127;
    int h  = (idx >> 7) & 127;
    int cp = (idx >> 14) & 31;
    int b  = idx >> 19;
    int q  = cp >> 3, cc = cp & 7;
    int sh = h + ((q >> 1) << 7);
    int sw = w + ((q & 1) << 7);
    g_ysg[idx] = g_yin[(size_t)(b*32 + 24 + cc)*65536 + sh*256 + sw];
}

// ---------------- warp FFT (radix-2 DIT, in-place, bit-reversal) ----------------
template<int N, bool INV>
__device__ __forceinline__ void warp_fft(float2* s, int lane) {
    constexpr int LOG2N = (N == 256) ? 8 : 7;
    const float2* tw = (N == 256) ? g_tw256 : g_tw128;
    #pragma unroll
    for (int i = lane; i < N; i += 32) {
        int r = (int)(__brev((unsigned)i) >> (32 - LOG2N));
        if (r > i) { float2 a = s[i]; s[i] = s[r]; s[r] = a; }
    }
    __syncwarp();
    #pragma unroll
    for (int len = 2; len <= N; len <<= 1) {
        int half = len >> 1;
        int tstr = N / len;
        #pragma unroll
        for (int t = lane; t < (N >> 1); t += 32) {
            int j  = t & (half - 1);
            int i1 = 2*t - j;
            int i2 = i1 + half;
            float2 w = tw[j * tstr];
            float wy = INV ? -w.y : w.y;
            float2 u = s[i1], v = s[i2];
            float vx = v.x*w.x - v.y*wy;
            float vy = v.x*wy + v.y*w.x;
            s[i1] = make_float2(u.x + vx, u.y + vy);
            s[i2] = make_float2(u.x - vx, u.y - vy);
        }
        __syncwarp();
    }
}

// ---------------- forward: rfft along rows (real in -> half spectrum) ----------------
template<int N>
__global__ void k_fft_row_fwd() {
    constexpr int Wf = N/2 + 1;
    __shared__ float2 smf[8*N];
    int img  = blockIdx.y;
    int wid  = threadIdx.x >> 5, lane = threadIdx.x & 31;
    int h    = blockIdx.x*8 + wid;
    float2* s = smf + wid*N;
    const float* in = (N == 256) ? g_yin : g_ysg;
    const float* row = in + (size_t)img*N*N + (size_t)h*N;
    #pragma unroll
    for (int i = lane; i < N; i += 32) s[i] = make_float2(row[i], 0.f);
    __syncwarp();
    warp_fft<N, false>(s, lane);
    float2* F = (N == 256) ? g_F1 : g_F2;
    float2* orow = F + (size_t)img*N*Wf + (size_t)h*Wf;
    for (int i = lane; i < Wf; i += 32) orow[i] = s[i];
}

// ---------------- forward: complex fft along columns (in place) ----------------
template<int N>
__global__ void k_fft_col_fwd() {
    constexpr int Wf = N/2 + 1;
    __shared__ float2 smf[8*N];
    int img = blockIdx.y;
    int wid = threadIdx.x >> 5, lane = threadIdx.x & 31;
    int wf  = blockIdx.x*8 + wid;
    if (wf >= Wf) return;
    float2* s = smf + wid*N;
    float2* F = (N == 256) ? g_F1 : g_F2;
    float2* col = F + (size_t)img*N*Wf + wf;
    for (int i = lane; i < N; i += 32) s[i] = col[(size_t)i*Wf];
    __syncwarp();
    warp_fft<N, false>(s, lane);
    for (int i = lane; i < N; i += 32) col[(size_t)i*Wf] = s[i];
}

// ---------------- frequency-domain 64x64 conv1x1 ----------------
template<int N>
__global__ void k_convfreq(const float* __restrict__ w, const float* __restrict__ bias) {
    constexpr int Wf = N/2 + 1;
    constexpr int S  = N * Wf;
    __shared__ __align__(16) float Ws[64*65];
    __shared__ __align__(16) float Xs[64*64];
    const float2* F  = (N == 256) ? g_F1  : g_F2;
    float*        YC = (N == 256) ? g_YC1 : g_YC2;
    int b = blockIdx.y, p0 = blockIdx.x*64, t = threadIdx.x;
    for (int i = t; i < 64*64; i += 256) Ws[(i>>6)*65 + (i&63)] = w[i];
    for (int i = t; i < 32*64; i += 256) {
        int c = i >> 6, p = i & 63;
        float2 v = F[(size_t)(b*32 + c)*S + p0 + p];
        Xs[c*64 + p]      = v.x;
        Xs[(32+c)*64 + p] = v.y;
    }
    __syncthreads();
    int rg = t >> 4, pg = t & 15;
    float acc[4][4] = {};
    #pragma unroll
    for (int k = 0; k < 64; k++) {
        float4 xf = *(const float4*)&Xs[k*64 + pg*4];
        #pragma unroll
        for (int r = 0; r < 4; r++) {
            float wv = Ws[(rg*4 + r)*65 + k];
            acc[r][0] += wv*xf.x; acc[r][1] += wv*xf.y;
            acc[r][2] += wv*xf.z; acc[r][3] += wv*xf.w;
        }
    }
    #pragma unroll
    for (int r = 0; r < 4; r++) {
        int o = rg*4 + r;
        float bo = bias[o];
        float4 res = make_float4(acc[r][0]+bo, acc[r][1]+bo, acc[r][2]+bo, acc[r][3]+bo);
        *(float4*)&YC[(size_t)(b*64 + o)*S + p0 + pg*4] = res;
    }
}

// ---------------- BN stats (deterministic two-stage) ----------------
template<int N>
__global__ void k_stats() {
    constexpr int S = N * (N/2 + 1);
    const float* YC  = (N == 256) ? g_YC1  : g_YC2;
    float*      part = (N == 256) ? g_part1 : g_part2;
    int o = blockIdx.x, b = blockIdx.y;
    const float* p = YC + (size_t)(b*64 + o)*S;
    float s = 0.f, s2 = 0.f;
    for (int i = threadIdx.x; i < S; i += 256) { float v = p[i]; s += v; s2 += v*v; }
    __shared__ float rs[256], rq[256];
    rs[threadIdx.x] = s; rq[threadIdx.x] = s2;
    __syncthreads();
    for (int d = 128; d > 0; d >>= 1) {
        if (threadIdx.x < d) { rs[threadIdx.x] += rs[threadIdx.x+d]; rq[threadIdx.x] += rq[threadIdx.x+d]; }
        __syncthreads();
    }
    if (threadIdx.x == 0) {
        part[(b*64 + o)*2]     = rs[0];
        part[(b*64 + o)*2 + 1] = rq[0];
    }
}

template<int N>
__global__ void k_bnfin(const float* __restrict__ gamma, const float* __restrict__ beta) {
    constexpr int S = N * (N/2 + 1);
    const float* part = (N == 256) ? g_part1  : g_part2;
    float* scale      = (N == 256) ? g_scale1 : g_scale2;
    float* shift      = (N == 256) ? g_shift1 : g_shift2;
    int o = threadIdx.x;
    if (o < 64) {
        float s = 0.f, s2 = 0.f;
        for (int b = 0; b < 4; b++) { s += part[(b*64+o)*2]; s2 += part[(b*64+o)*2 + 1]; }
        float np  = 4.0f * (float)S;
        float mu  = s / np;
        float var = s2 / np - mu*mu;
        float sc  = gamma[o] * rsqrtf(var + 1e-5f);
        scale[o] = sc;
        shift[o] = beta[o] - mu*sc;
    }
}

// ---------------- inverse column pass: BN+ReLU + Hermitian fix + ifft(h) ----------------
template<int N>
__global__ void k_ifft_col() {
    constexpr int Wf = N/2 + 1;
    constexpr int S  = N * Wf;
    __shared__ float2 smf[8*N];
    int img = blockIdx.y;
    int b = img >> 5, c = img & 31;
    int wid = threadIdx.x >> 5, lane = threadIdx.x & 31;
    int wf = blockIdx.x*8 + wid;
    if (wf >= Wf) return;
    const float* YC    = (N == 256) ? g_YC1   : g_YC2;
    const float* scale = (N == 256) ? g_scale1 : g_scale2;
    const float* shift = (N == 256) ? g_shift1 : g_shift2;
    float2* F = (N == 256) ? g_F1 : g_F2;
    float sr = scale[c],    hr = shift[c];
    float si = scale[32+c], hi = shift[32+c];
    const float* yr = YC + (size_t)(b*64 + c)*S + wf;
    const float* yi = YC + (size_t)(b*64 + 32 + c)*S + wf;
    float2* s = smf + wid*N;
    for (int h = lane; h < N; h += 32) {
        float a = yr[(size_t)h*Wf]*sr + hr; a = a > 0.f ? a : 0.f;
        float g = yi[(size_t)h*Wf]*si + hi; g = g > 0.f ? g : 0.f;
        s[h] = make_float2(a, g);
    }
    __syncwarp();
    if (wf == 0 || wf == N/2) {
        float2 tmp[N/32];
        #pragma unroll
        for (int k = 0; k < N/32; k++) {
            int h = lane + 32*k;
            float2 a = s[h];
            float2 m = s[(N - h) & (N - 1)];
            tmp[k] = make_float2(0.5f*(a.x + m.x), 0.5f*(a.y - m.y));
        }
        __syncwarp();
        #pragma unroll
        for (int k = 0; k < N/32; k++) s[lane + 32*k] = tmp[k];
        __syncwarp();
    }
    warp_fft<N, true>(s, lane);
    float2* col = F + (size_t)img*N*Wf + wf;
    constexpr float inv = 1.0f / (float)N;
    for (int h = lane; h < N; h += 32)
        col[(size_t)h*Wf] = make_float2(s[h].x*inv, s[h].y*inv);
}

// ---------------- inverse row pass: irfft(w) -> real spatial ----------------
template<int N>
__global__ void k_ifft_row() {
    constexpr int Wf = N/2 + 1;
    __shared__ float2 smf[8*N];
    int img = blockIdx.y;
    int wid = threadIdx.x >> 5, lane = threadIdx.x & 31;
    int h = blockIdx.x*8 + wid;
    const float2* F = (N == 256) ? g_F1 : g_F2;
    const float2* row = F + (size_t)img*N*Wf + (size_t)h*Wf;
    float2* s = smf + wid*N;
    for (int w = lane; w < N; w += 32) {
        if (w < Wf) s[w] = row[w];
        else { float2 v = row[N - w]; s[w] = make_float2(v.x, -v.y); }
    }
    __syncwarp();
    warp_fft<N, true>(s, lane);
    float* out = (N == 256) ? g_yg : g_yfu2;
    float* orow = out + (size_t)img*N*N + (size_t)h*N;
    constexpr float inv = 1.0f / (float)N;
    for (int w = lane; w < N; w += 32) orow[w] = s[w].x * inv;
}

// ---------------- final conv: d_out[0:64] += w_out @ (y_g + tile(y_fu2)) + b_out ----------------
__global__ void k_out(float* __restrict__ out, const float* __restrict__ w, const float* __restrict__ bias) {
    __shared__ __align__(16) float Ws[64*33];
    __shared__ __align__(16) float Xs[32*64];
    int b = blockIdx.y, p0 = blockIdx.x*64, t = threadIdx.x;
    for (int i = t; i < 64*32; i += 256) Ws[(i>>5)*33 + (i&31)] = w[i];
    int hh = p0 >> 8, w0 = p0 & 255;
    int foff = ((hh & 127) << 7) + (w0 & 127);
    for (int i = t; i < 32*64; i += 256) {
        int c = i >> 6, p = i & 63;
        Xs[i] = g_yg[(size_t)(b*32 + c)*65536 + p0 + p]
              + g_yfu2[(size_t)(b*32 + c)*16384 + foff + p];
    }
    __syncthreads();
    int rg = t >> 4, pg = t & 15;
    float acc[4][4] = {};
    #pragma unroll
    for (int k = 0; k < 32; k++) {
        float4 xf = *(const float4*)&Xs[k*64 + pg*4];
        #pragma unroll
        for (int r = 0; r < 4; r++) {
            float wv = Ws[(rg*4 + r)*33 + k];
            acc[r][0] += wv*xf.x; acc[r][1] += wv*xf.y;
            acc[r][2] += wv*xf.z; acc[r][3] += wv*xf.w;
        }
    }
    #pragma unroll
    for (int r = 0; r < 4; r++) {
        int o = rg*4 + r;
        float bo = bias[o];
        size_t idx = (size_t)(b*128 + o)*65536 + p0 + pg*4;
        float4 cur = *(float4*)&out[idx];
        cur.x += acc[r][0] + bo; cur.y += acc[r][1] + bo;
        cur.z += acc[r][2] + bo; cur.w += acc[r][3] + bo;
        *(float4*)&out[idx] = cur;
    }
}

// ---------------- host ----------------
static const int CONV_MAIN_SMEM = (160*129 + 128*64) * 4;  // 115,328 B

extern "C" void kernel_launch(void* const* d_in, const int* in_sizes, int n_in,
                              void* d_out, int out_size) {
    const float* x       = (const float*)d_in[0];
    const float* w_local = (const float*)d_in[1];
    const float* b_local = (const float*)d_in[2];
    const float* w_in    = (const float*)d_in[3];
    const float* b_in    = (const float*)d_in[4];
    const float* w_outp  = (const float*)d_in[5];
    const float* b_outp  = (const float*)d_in[6];
    const float* w_g2l   = (const float*)d_in[7];
    const float* b_g2l   = (const float*)d_in[8];
    const float* w_l2g   = (const float*)d_in[9];
    const float* b_l2g   = (const float*)d_in[10];
    const float* w_fu1   = (const float*)d_in[11];
    const float* b_fu1   = (const float*)d_in[12];
    const float* gm_fu1  = (const float*)d_in[13];
    const float* be_fu1  = (const float*)d_in[14];
    const float* w_fu2   = (const float*)d_in[15];
    const float* b_fu2   = (const float*)d_in[16];
    const float* gm_fu2  = (const float*)d_in[17];
    const float* be_fu2  = (const float*)d_in[18];
    float* out = (float*)d_out;

    cudaFuncSetAttribute(k_conv_main, cudaFuncAttributeMaxDynamicSharedMemorySize, CONV_MAIN_SMEM);

    k_prep<<<1, 256>>>(w_local, b_local, w_in, b_in, w_g2l, b_g2l, w_l2g, b_l2g);
    k_conv_main<<<dim3(1024, 4), 256, CONV_MAIN_SMEM>>>(x, out);
    k_quad<<<(4*32*128*128)/256, 256>>>();

    // FU1 (N=256)
    k_fft_row_fwd<256><<<dim3(32, 128), 256>>>();
    k_fft_col_fwd<256><<<dim3(17, 128), 256>>>();
    k_convfreq<256><<<dim3(516, 4), 256>>>(w_fu1, b_fu1);
    k_stats<256><<<dim3(64, 4), 256>>>();
    k_bnfin<256><<<1, 64>>>(gm_fu1, be_fu1);
    k_ifft_col<256><<<dim3(17, 128), 256>>>();
    k_ifft_row<256><<<dim3(32, 128), 256>>>();

    // FU2 (N=128)
    k_fft_row_fwd<128><<<dim3(16, 128), 256>>>();
    k_fft_col_fwd<128><<<dim3(9, 128), 256>>>();
    k_convfreq<128><<<dim3(130, 4), 256>>>(w_fu2, b_fu2);
    k_stats<128><<<dim3(64, 4), 256>>>();
    k_bnfin<128><<<1, 64>>>(gm_fu2, be_fu2);
    k_ifft_col<128><<<dim3(9, 128), 256>>>();
    k_ifft_row<128><<<dim3(16, 128), 256>>>();

    k_out<<<dim3(1024, 4), 256>>>(out, w_outp, b_outp);
}

// round 8
// speedup vs baseline: 1.4599x; 1.4599x over previous
#include <cuda_runtime.h>
#include <cstdint>
#include <math.h>

#define PI_D 3.14159265358979323846

// ---------------- scratch (device globals; allocation-free) ----------------
__device__ __align__(16) float  g_yin [4*32*65536];       // y_in (4,32,256,256)
__device__ __align__(16) float  g_ysg [4*32*128*128];     // quadrant-stacked
__device__ __align__(16) float2 g_F1  [4*32*129*256];     // FU1 spectrum, [img][wf][h]
__device__ __align__(16) float2 g_F2  [4*32*65*128];      // FU2 spectrum, [img][wf][h]
__device__ __align__(16) float  g_YC1 [4*64*129*256];     // FU1 freq conv out (flat pixels)
__device__ __align__(16) float  g_YC2 [4*64*65*128];
__device__ __align__(16) float  g_yg  [4*32*65536];       // FU1 output (spatial)
__device__ __align__(16) float  g_yfu2[4*32*128*128];     // FU2 output (spatial)
__device__ __align__(16) float  g_Wbig[160*128];
__device__ float  g_bbig[160];
__device__ __align__(16) float2 g_wt[256];                // W256^i = exp(-2*pi*i*I/256)
__device__ float  g_part1[4*64*2];
__device__ float  g_part2[4*64*2];
__device__ float  g_scale1[64], g_shift1[64];
__device__ float  g_scale2[64], g_shift2[64];

// ---------------- f32x2 helpers ----------------
__device__ __forceinline__ unsigned long long fma2(unsigned long long a, unsigned long long b, unsigned long long c) {
    unsigned long long d;
    asm("fma.rn.f32x2 %0, %1, %2, %3;" : "=l"(d) : "l"(a), "l"(b), "l"(c));
    return d;
}
__device__ __forceinline__ unsigned long long pack2(float x, float y) {
    unsigned long long d; asm("mov.b64 %0, {%1,%2};" : "=l"(d) : "f"(x), "f"(y)); return d;
}
__device__ __forceinline__ float2 unpack2(unsigned long long a) {
    float2 r; asm("mov.b64 {%0,%1}, %2;" : "=f"(r.x), "=f"(r.y) : "l"(a)); return r;
}

// ---------------- complex helpers ----------------
__device__ __forceinline__ float2 cadd(float2 a, float2 b){ return make_float2(a.x+b.x, a.y+b.y); }
__device__ __forceinline__ float2 csub(float2 a, float2 b){ return make_float2(a.x-b.x, a.y-b.y); }
__device__ __forceinline__ float2 cmul(float2 a, float2 b){
    return make_float2(fmaf(a.x, b.x, -a.y*b.y), fmaf(a.x, b.y, a.y*b.x));
}
template<bool INV>
__device__ __forceinline__ float2 twd(int idx) {   // W256^idx (conj for inverse)
    float2 w = g_wt[idx];
    if (INV) w.y = -w.y;
    return w;
}
__device__ __forceinline__ int br_idx(int R, int i) {
    if (R == 8) { const int t[8] = {0,4,2,6,1,5,3,7}; return t[i]; }
    else        { const int t[4] = {0,2,1,3};         return t[i]; }
}

// ---------------- prep: twiddle table + fused weight matrix ----------------
__global__ void k_prep(const float* __restrict__ w_local, const float* __restrict__ b_local,
                       const float* __restrict__ w_in,    const float* __restrict__ b_in,
                       const float* __restrict__ w_g2l,   const float* __restrict__ b_g2l,
                       const float* __restrict__ w_l2g,   const float* __restrict__ b_l2g) {
    int t = threadIdx.x;
    for (int i = t; i < 256; i += 256) {
        double a = -2.0 * PI_D * (double)i / 256.0;
        g_wt[i] = make_float2((float)cos(a), (float)sin(a));
    }
    for (int i = t; i < 160*128; i += 256) {
        int row = i >> 7, c = i & 127; float v;
        if (row < 64)        v = (c >= 64) ? w_l2g[row*64 + (c-64)] : 0.f;
        else if (row < 128) { int o = row-64; v = (c < 64) ? w_g2l[o*64+c] : w_local[o*64 + (c-64)]; }
        else               { int o = row-128; v = (c < 64) ? w_in[o*64+c] : 0.f; }
        g_Wbig[i] = v;
    }
    for (int i = t; i < 160; i += 256) {
        float v;
        if (i < 64)       v = b_l2g[i];
        else if (i < 128) v = b_g2l[i-64] + b_local[i-64];
        else              v = b_in[i-128];
        g_bbig[i] = v;
    }
}

// ---------------- main fused conv: x -> d_out(128ch init) + y_in(32ch) ----------------
__global__ void k_conv_main(const float* __restrict__ x, float* __restrict__ out) {
    extern __shared__ __align__(16) float sm[];
    float* Ws = sm;              // 160*129
    float* Xs = sm + 160*129;    // 128*64 (16B aligned: 160*129*4 = 82560)
    int b  = blockIdx.y;
    int p0 = blockIdx.x * 64;
    int t  = threadIdx.x;
    for (int i = t; i < 160*128; i += 256) Ws[(i>>7)*129 + (i&127)] = g_Wbig[i];
    const float* xb = x + (size_t)b*128*65536 + p0;
    for (int i = t; i < 128*64; i += 256) Xs[i] = xb[(size_t)(i>>6)*65536 + (i&63)];
    __syncthreads();
    int rg = t >> 4, pg = t & 15;
    unsigned long long a0[10], a1[10];
    #pragma unroll
    for (int r = 0; r < 10; r++) { a0[r] = 0ull; a1[r] = 0ull; }
    const float* wp = Ws + rg*10*129;
    #pragma unroll 4
    for (int k = 0; k < 128; k++) {
        ulonglong2 xf = *(const ulonglong2*)&Xs[k*64 + pg*4];
        #pragma unroll
        for (int r = 0; r < 10; r++) {
            float wv = wp[r*129 + k];
            unsigned long long w2 = pack2(wv, wv);
            a0[r] = fma2(w2, xf.x, a0[r]);
            a1[r] = fma2(w2, xf.y, a1[r]);
        }
    }
    #pragma unroll
    for (int r = 0; r < 10; r++) {
        int row = rg*10 + r;
        float bo = g_bbig[row];
        float2 lo = unpack2(a0[r]), hi = unpack2(a1[r]);
        float4 res = make_float4(lo.x+bo, lo.y+bo, hi.x+bo, hi.y+bo);
        if (row < 128) *(float4*)&out  [(size_t)(b*128+row)*65536     + p0 + pg*4] = res;
        else           *(float4*)&g_yin[(size_t)(b*32 +row-128)*65536 + p0 + pg*4] = res;
    }
}

// ---------------- quadrant stack for FU2 ----------------
__global__ void k_quad() {
    int idx = blockIdx.x*256 + threadIdx.x;           // total 2^21
    int w  = idx & 127;
    int h  = (idx >> 7) & 127;
    int cp = (idx >> 14) & 31;
    int b  = idx >> 19;
    int q  = cp >> 3, cc = cp & 7;
    int sh = h + ((q >> 1) << 7);
    int sw = w + ((q & 1) << 7);
    g_ysg[idx] = g_yin[(size_t)(b*32 + 24 + cc)*65536 + sh*256 + sw];
}

// ---------------- register/shuffle FFT: N = 32*R, DIF, natural-in, chunked-out ----------------
// Input:  v[j] = x[lane + 32*j]
// Output: v[r] holds X[R*lane + br(r)]  (forward: W^-; INV: W^+, no scaling)
template<int R, bool INV>
__device__ __forceinline__ void fft_dif(float2 v[R], int lane) {
    // register stage: R-point DIF over j
    if (R == 8) {
        const float c = 0.70710678118654752f;
        const float sg = INV ? 1.f : -1.f;
        float2 w1 = make_float2( c, sg*c);
        float2 w2 = make_float2(0.f, sg);
        float2 w3 = make_float2(-c, sg*c);
        float2 t;
        t=v[0]; v[0]=cadd(t,v[4]); v[4]=csub(t,v[4]);
        t=v[1]; v[1]=cadd(t,v[5]); v[5]=cmul(csub(t,v[5]), w1);
        t=v[2]; v[2]=cadd(t,v[6]); v[6]=cmul(csub(t,v[6]), w2);
        t=v[3]; v[3]=cadd(t,v[7]); v[7]=cmul(csub(t,v[7]), w3);
        t=v[0]; v[0]=cadd(t,v[2]); v[2]=csub(t,v[2]);
        t=v[1]; v[1]=cadd(t,v[3]); v[3]=cmul(csub(t,v[3]), w2);
        t=v[4]; v[4]=cadd(t,v[6]); v[6]=csub(t,v[6]);
        t=v[5]; v[5]=cadd(t,v[7]); v[7]=cmul(csub(t,v[7]), w2);
        t=v[0]; v[0]=cadd(t,v[1]); v[1]=csub(t,v[1]);
        t=v[2]; v[2]=cadd(t,v[3]); v[3]=csub(t,v[3]);
        t=v[4]; v[4]=cadd(t,v[5]); v[5]=csub(t,v[5]);
        t=v[6]; v[6]=cadd(t,v[7]); v[7]=csub(t,v[7]);
    } else {  // R == 4
        const float sg = INV ? 1.f : -1.f;
        float2 w2 = make_float2(0.f, sg);
        float2 t;
        t=v[0]; v[0]=cadd(t,v[2]); v[2]=csub(t,v[2]);
        t=v[1]; v[1]=cadd(t,v[3]); v[3]=cmul(csub(t,v[3]), w2);
        t=v[0]; v[0]=cadd(t,v[1]); v[1]=csub(t,v[1]);
        t=v[2]; v[2]=cadd(t,v[3]); v[3]=csub(t,v[3]);
    }
    // inter-stage twiddle: v[br(k1)] *= W_N^{lane*k1}, N = 32R
    {
        const int step = 256 / (32*R);
        float2 w1 = twd<INV>(lane * step);
        float2 w = w1;
        if (R == 8) {
            v[4]=cmul(v[4],w); w=cmul(w,w1);
            v[2]=cmul(v[2],w); w=cmul(w,w1);
            v[6]=cmul(v[6],w); w=cmul(w,w1);
            v[1]=cmul(v[1],w); w=cmul(w,w1);
            v[5]=cmul(v[5],w); w=cmul(w,w1);
            v[3]=cmul(v[3],w); w=cmul(w,w1);
            v[7]=cmul(v[7],w);
        } else {
            v[2]=cmul(v[2],w); w=cmul(w,w1);
            v[1]=cmul(v[1],w); w=cmul(w,w1);
            v[3]=cmul(v[3],w);
        }
    }
    // lane stage: 32-point DIF across lanes (shfl_xor), twiddles W32^e = W256^{8e}
    float2 wh16 = twd<INV>((lane & 15) * 8);
    float2 wh8  = twd<INV>((lane & 7)  * 16);
    float2 wh4  = twd<INV>((lane & 3)  * 32);
    float2 wh2  = twd<INV>((lane & 1)  * 64);
    #pragma unroll
    for (int r = 0; r < R; r++) {
        float2 x = v[r], o;
        o.x = __shfl_xor_sync(0xffffffffu, x.x, 16); o.y = __shfl_xor_sync(0xffffffffu, x.y, 16);
        x = (lane & 16) ? cmul(csub(o, x), wh16) : cadd(x, o);
        o.x = __shfl_xor_sync(0xffffffffu, x.x, 8);  o.y = __shfl_xor_sync(0xffffffffu, x.y, 8);
        x = (lane & 8)  ? cmul(csub(o, x), wh8)  : cadd(x, o);
        o.x = __shfl_xor_sync(0xffffffffu, x.x, 4);  o.y = __shfl_xor_sync(0xffffffffu, x.y, 4);
        x = (lane & 4)  ? cmul(csub(o, x), wh4)  : cadd(x, o);
        o.x = __shfl_xor_sync(0xffffffffu, x.x, 2);  o.y = __shfl_xor_sync(0xffffffffu, x.y, 2);
        x = (lane & 2)  ? cmul(csub(o, x), wh2)  : cadd(x, o);
        o.x = __shfl_xor_sync(0xffffffffu, x.x, 1);  o.y = __shfl_xor_sync(0xffffffffu, x.y, 1);
        x = (lane & 1)  ? csub(o, x) : cadd(x, o);
        v[r] = x;
    }
    // unscramble lanes (bitrev5 is an involution)
    int src = __brev((unsigned)lane) >> 27;
    #pragma unroll
    for (int r = 0; r < R; r++) {
        v[r].x = __shfl_sync(0xffffffffu, v[r].x, src);
        v[r].y = __shfl_sync(0xffffffffu, v[r].y, src);
    }
}

// ---------------- row forward: spatial rows -> F^T[wf][h] (wf <= N/2) ----------------
template<int N>
__global__ void k_fft_row_fwd() {
    constexpr int R  = N/32;
    constexpr int Wf = N/2 + 1;
    constexpr int TS = (N == 256) ? 353 : 175;   // odd row stride, >= max(p(k))+1
    __shared__ float2 tile[8][TS];
    int img = blockIdx.y;
    int wid = threadIdx.x >> 5, lane = threadIdx.x & 31;
    int h0  = blockIdx.x * 8;
    const float* in = (N == 256) ? g_yin : g_ysg;
    const float* row = in + (size_t)img*N*N + (size_t)(h0 + wid)*N;
    float2 v[R];
    #pragma unroll
    for (int j = 0; j < R; j++) v[j] = make_float2(row[lane + 32*j], 0.f);
    fft_dif<R, false>(v, lane);
    #pragma unroll
    for (int i = 0; i < R; i++) {
        int k = R*lane + i;
        if (k <= N/2) tile[wid][k + 3*(k>>3)] = v[br_idx(R, i)];
    }
    __syncthreads();
    float2* F  = (N == 256) ? g_F1 : g_F2;
    float2* Fi = F + (size_t)img*Wf*N;
    for (int i = threadIdx.x; i < Wf*8; i += 256) {
        int wf = i >> 3, hh = i & 7;
        Fi[(size_t)wf*N + h0 + hh] = tile[hh][wf + 3*(wf>>3)];
    }
}

// ---------------- column forward: in-place on F^T (contiguous columns) ----------------
template<int N>
__global__ void k_fft_col_fwd() {
    constexpr int R  = N/32;
    constexpr int Wf = N/2 + 1;
    int img = blockIdx.y;
    int wid = threadIdx.x >> 5, lane = threadIdx.x & 31;
    int wf  = blockIdx.x*8 + wid;
    if (wf >= Wf) return;
    float2* F   = (N == 256) ? g_F1 : g_F2;
    float2* col = F + (size_t)img*Wf*N + (size_t)wf*N;
    float2 v[R];
    #pragma unroll
    for (int j = 0; j < R; j++) v[j] = col[lane + 32*j];
    fft_dif<R, false>(v, lane);
    float2 c[R];
    #pragma unroll
    for (int i = 0; i < R; i++) c[i] = v[br_idx(R, i)];
    float4* dst = (float4*)(col + R*lane);
    #pragma unroll
    for (int i = 0; i < R/2; i++)
        dst[i] = make_float4(c[2*i].x, c[2*i].y, c[2*i+1].x, c[2*i+1].y);
}

// ---------------- frequency-domain 64x64 conv1x1 (flat pixels; layout-agnostic) ----------------
template<int N>
__global__ void k_convfreq(const float* __restrict__ w, const float* __restrict__ bias) {
    constexpr int Wf = N/2 + 1;
    constexpr int S  = N * Wf;
    __shared__ __align__(16) float Ws[64*65];
    __shared__ __align__(16) float Xs[64*64];
    const float2* F  = (N == 256) ? g_F1  : g_F2;
    float*        YC = (N == 256) ? g_YC1 : g_YC2;
    int b = blockIdx.y, p0 = blockIdx.x*64, t = threadIdx.x;
    for (int i = t; i < 64*64; i += 256) Ws[(i>>6)*65 + (i&63)] = w[i];
    for (int i = t; i < 32*64; i += 256) {
        int c = i >> 6, p = i & 63;
        float2 v = F[(size_t)(b*32 + c)*S + p0 + p];
        Xs[c*64 + p]      = v.x;
        Xs[(32+c)*64 + p] = v.y;
    }
    __syncthreads();
    int rg = t >> 4, pg = t & 15;
    unsigned long long a0[4], a1[4];
    #pragma unroll
    for (int r = 0; r < 4; r++) { a0[r] = 0ull; a1[r] = 0ull; }
    #pragma unroll 4
    for (int k = 0; k < 64; k++) {
        ulonglong2 xf = *(const ulonglong2*)&Xs[k*64 + pg*4];
        #pragma unroll
        for (int r = 0; r < 4; r++) {
            float wv = Ws[(rg*4 + r)*65 + k];
            unsigned long long w2 = pack2(wv, wv);
            a0[r] = fma2(w2, xf.x, a0[r]);
            a1[r] = fma2(w2, xf.y, a1[r]);
        }
    }
    #pragma unroll
    for (int r = 0; r < 4; r++) {
        int o = rg*4 + r;
        float bo = bias[o];
        float2 lo = unpack2(a0[r]), hi = unpack2(a1[r]);
        float4 res = make_float4(lo.x+bo, lo.y+bo, hi.x+bo, hi.y+bo);
        *(float4*)&YC[(size_t)(b*64 + o)*S + p0 + pg*4] = res;
    }
}

// ---------------- BN stats (deterministic two-stage) ----------------
template<int N>
__global__ void k_stats() {
    constexpr int S = N * (N/2 + 1);
    const float* YC  = (N == 256) ? g_YC1  : g_YC2;
    float*      part = (N == 256) ? g_part1 : g_part2;
    int o = blockIdx.x, b = blockIdx.y;
    const float* p = YC + (size_t)(b*64 + o)*S;
    float s = 0.f, s2 = 0.f;
    for (int i = threadIdx.x; i < S; i += 256) { float v = p[i]; s += v; s2 += v*v; }
    __shared__ float rs[256], rq[256];
    rs[threadIdx.x] = s; rq[threadIdx.x] = s2;
    __syncthreads();
    for (int d = 128; d > 0; d >>= 1) {
        if (threadIdx.x < d) { rs[threadIdx.x] += rs[threadIdx.x+d]; rq[threadIdx.x] += rq[threadIdx.x+d]; }
        __syncthreads();
    }
    if (threadIdx.x == 0) {
        part[(b*64 + o)*2]     = rs[0];
        part[(b*64 + o)*2 + 1] = rq[0];
    }
}

template<int N>
__global__ void k_bnfin(const float* __restrict__ gamma, const float* __restrict__ beta) {
    constexpr int S = N * (N/2 + 1);
    const float* part = (N == 256) ? g_part1  : g_part2;
    float* scale      = (N == 256) ? g_scale1 : g_scale2;
    float* shift      = (N == 256) ? g_shift1 : g_shift2;
    int o = threadIdx.x;
    if (o < 64) {
        float s = 0.f, s2 = 0.f;
        for (int b = 0; b < 4; b++) { s += part[(b*64+o)*2]; s2 += part[(b*64+o)*2 + 1]; }
        float np  = 4.0f * (float)S;
        float mu  = s / np;
        float var = s2 / np - mu*mu;
        float sc  = gamma[o] * rsqrtf(var + 1e-5f);
        scale[o] = sc;
        shift[o] = beta[o] - mu*sc;
    }
}

// ---------------- inverse column pass: BN+ReLU + Hermitian fix + ifft(h) ----------------
template<int N>
__global__ void k_ifft_col() {
    constexpr int R  = N/32;
    constexpr int Wf = N/2 + 1;
    constexpr int S  = Wf * N;
    __shared__ float2 ht[8][352];
    int img = blockIdx.y;
    int b = img >> 5, ch = img & 31;
    int wid = threadIdx.x >> 5, lane = threadIdx.x & 31;
    int wf = blockIdx.x*8 + wid;
    if (wf >= Wf) return;
    const float* YC    = (N == 256) ? g_YC1   : g_YC2;
    const float* scale = (N == 256) ? g_scale1 : g_scale2;
    const float* shift = (N == 256) ? g_shift1 : g_shift2;
    float sr = scale[ch],    hr = shift[ch];
    float si = scale[32+ch], hi = shift[32+ch];
    const float* yr = YC + (size_t)(b*64 + ch)*S      + (size_t)wf*N;
    const float* yi = YC + (size_t)(b*64 + 32 + ch)*S + (size_t)wf*N;
    float2 v[R];
    #pragma unroll
    for (int j = 0; j < R; j++) {
        int n = lane + 32*j;
        float a = fmaf(yr[n], sr, hr); a = fmaxf(a, 0.f);
        float g = fmaf(yi[n], si, hi); g = fmaxf(g, 0.f);
        v[j] = make_float2(a, g);
    }
    if (wf == 0 || wf == N/2) {    // Hermitian symmetrization along h at these 2 columns
        #pragma unroll
        for (int j = 0; j < R; j++) { int n = lane + 32*j; ht[wid][n + 3*(n>>3)] = v[j]; }
        __syncwarp();
        #pragma unroll
        for (int j = 0; j < R; j++) {
            int n = lane + 32*j;
            int m = (N - n) & (N - 1);
            float2 z2 = ht[wid][m + 3*(m>>3)];
            v[j] = make_float2(0.5f*(v[j].x + z2.x), 0.5f*(v[j].y - z2.y));
        }
    }
    fft_dif<R, true>(v, lane);
    float2* F   = (N == 256) ? g_F1 : g_F2;
    float2* col = F + (size_t)img*S + (size_t)wf*N;
    float2 c[R];
    #pragma unroll
    for (int i = 0; i < R; i++) c[i] = v[br_idx(R, i)];
    float4* dst = (float4*)(col + R*lane);
    #pragma unroll
    for (int i = 0; i < R/2; i++)
        dst[i] = make_float4(c[2*i].x, c[2*i].y, c[2*i+1].x, c[2*i+1].y);
}

// ---------------- inverse row pass: Hermitian extend + ifft(w) -> real, scale 1/N^2 ----------------
template<int N>
__global__ void k_ifft_row() {
    constexpr int R  = N/32;
    constexpr int Wf = N/2 + 1;                   // odd -> conflict-friendly stride
    __shared__ float2 tile[8][Wf];
    int img = blockIdx.y;
    int wid = threadIdx.x >> 5, lane = threadIdx.x & 31;
    int h0 = blockIdx.x * 8;
    const float2* F  = (N == 256) ? g_F1 : g_F2;
    const float2* Fi = F + (size_t)img*Wf*N;
    for (int i = threadIdx.x; i < Wf*8; i += 256) {
        int wf = i >> 3, hh = i & 7;
        tile[hh][wf] = Fi[(size_t)wf*N + h0 + hh];
    }
    __syncthreads();
    float2 v[R];
    #pragma unroll
    for (int j = 0; j < R; j++) {
        int n = lane + 32*j;
        if (n <= N/2) v[j] = tile[wid][n];
        else { float2 z = tile[wid][N - n]; v[j] = make_float2(z.x, -z.y); }
    }
    fft_dif<R, true>(v, lane);
    float* out  = (N == 256) ? g_yg : g_yfu2;
    float* orow = out + (size_t)img*N*N + (size_t)(h0 + wid)*N;
    const float s = 1.0f / ((float)N * (float)N);
    float c[R];
    #pragma unroll
    for (int i = 0; i < R; i++) c[i] = v[br_idx(R, i)].x * s;
    float4* dst = (float4*)(orow + R*lane);
    #pragma unroll
    for (int i = 0; i < R/4; i++)
        dst[i] = make_float4(c[4*i], c[4*i+1], c[4*i+2], c[4*i+3]);
}

// ---------------- final conv: d_out[0:64] += w_out @ (y_g + tile(y_fu2)) + b_out ----------------
__global__ void k_out(float* __restrict__ out, const float* __restrict__ w, const float* __restrict__ bias) {
    __shared__ __align__(16) float Ws[64*33];
    __shared__ __align__(16) float Xs[32*64];
    int b = blockIdx.y, p0 = blockIdx.x*64, t = threadIdx.x;
    for (int i = t; i < 64*32; i += 256) Ws[(i>>5)*33 + (i&31)] = w[i];
    int hh = p0 >> 8, w0 = p0 & 255;
    int foff = ((hh & 127) << 7) + (w0 & 127);
    for (int i = t; i < 32*64; i += 256) {
        int c = i >> 6, p = i & 63;
        Xs[i] = g_yg[(size_t)(b*32 + c)*65536 + p0 + p]
              + g_yfu2[(size_t)(b*32 + c)*16384 + foff + p];
    }
    __syncthreads();
    int rg = t >> 4, pg = t & 15;
    unsigned long long a0[4], a1[4];
    #pragma unroll
    for (int r = 0; r < 4; r++) { a0[r] = 0ull; a1[r] = 0ull; }
    #pragma unroll 4
    for (int k = 0; k < 32; k++) {
        ulonglong2 xf = *(const ulonglong2*)&Xs[k*64 + pg*4];
        #pragma unroll
        for (int r = 0; r < 4; r++) {
            float wv = Ws[(rg*4 + r)*33 + k];
            unsigned long long w2 = pack2(wv, wv);
            a0[r] = fma2(w2, xf.x, a0[r]);
            a1[r] = fma2(w2, xf.y, a1[r]);
        }
    }
    #pragma unroll
    for (int r = 0; r < 4; r++) {
        int o = rg*4 + r;
        float bo = bias[o];
        float2 lo = unpack2(a0[r]), hi = unpack2(a1[r]);
        size_t idx = (size_t)(b*128 + o)*65536 + p0 + pg*4;
        float4 cur = *(float4*)&out[idx];
        cur.x += lo.x + bo; cur.y += lo.y + bo;
        cur.z += hi.x + bo; cur.w += hi.y + bo;
        *(float4*)&out[idx] = cur;
    }
}

// ---------------- host ----------------
static const int CONV_MAIN_SMEM = (160*129 + 128*64) * 4;  // 115,328 B

extern "C" void kernel_launch(void* const* d_in, const int* in_sizes, int n_in,
                              void* d_out, int out_size) {
    const float* x       = (const float*)d_in[0];
    const float* w_local = (const float*)d_in[1];
    const float* b_local = (const float*)d_in[2];
    const float* w_in    = (const float*)d_in[3];
    const float* b_in    = (const float*)d_in[4];
    const float* w_outp  = (const float*)d_in[5];
    const float* b_outp  = (const float*)d_in[6];
    const float* w_g2l   = (const float*)d_in[7];
    const float* b_g2l   = (const float*)d_in[8];
    const float* w_l2g   = (const float*)d_in[9];
    const float* b_l2g   = (const float*)d_in[10];
    const float* w_fu1   = (const float*)d_in[11];
    const float* b_fu1   = (const float*)d_in[12];
    const float* gm_fu1  = (const float*)d_in[13];
    const float* be_fu1  = (const float*)d_in[14];
    const float* w_fu2   = (const float*)d_in[15];
    const float* b_fu2   = (const float*)d_in[16];
    const float* gm_fu2  = (const float*)d_in[17];
    const float* be_fu2  = (const float*)d_in[18];
    float* out = (float*)d_out;

    cudaFuncSetAttribute(k_conv_main, cudaFuncAttributeMaxDynamicSharedMemorySize, CONV_MAIN_SMEM);

    k_prep<<<1, 256>>>(w_local, b_local, w_in, b_in, w_g2l, b_g2l, w_l2g, b_l2g);
    k_conv_main<<<dim3(1024, 4), 256, CONV_MAIN_SMEM>>>(x, out);
    k_quad<<<(4*32*128*128)/256, 256>>>();

    // FU1 (N=256)
    k_fft_row_fwd<256><<<dim3(32, 128), 256>>>();
    k_fft_col_fwd<256><<<dim3(17, 128), 256>>>();
    k_convfreq<256><<<dim3(516, 4), 256>>>(w_fu1, b_fu1);
    k_stats<256><<<dim3(64, 4), 256>>>();
    k_bnfin<256><<<1, 64>>>(gm_fu1, be_fu1);
    k_ifft_col<256><<<dim3(17, 128), 256>>>();
    k_ifft_row<256><<<dim3(32, 128), 256>>>();

    // FU2 (N=128)
    k_fft_row_fwd<128><<<dim3(16, 128), 256>>>();
    k_fft_col_fwd<128><<<dim3(9, 128), 256>>>();
    k_convfreq<128><<<dim3(130, 4), 256>>>(w_fu2, b_fu2);
    k_stats<128><<<dim3(64, 4), 256>>>();
    k_bnfin<128><<<1, 64>>>(gm_fu2, be_fu2);
    k_ifft_col<128><<<dim3(9, 128), 256>>>();
    k_ifft_row<128><<<dim3(16, 128), 256>>>();

    k_out<<<dim3(1024, 4), 256>>>(out, w_outp, b_outp);
}